// round 12
// baseline (speedup 1.0000x reference)
#include <cuda_runtime.h>

// ProximalLSTMCell: N=256, D=512, H=512, EPS=1
// Matrix-free CG on (I + G G^T) p = c_new; G_n = diag(ci)Wi+diag(cf)Wf+diag(cg)Wg.
// R11: CG_ITERS 7->4. Measured: rel_err 3.3e-7 at 7 iters (fp32 floor) =>
// rho <= (3.3e-7)^(1/7) = 0.119; 4 iters => residual <= 2e-4, 5x inside 1e-3.
// GEMMs unchanged from R3 (64x64 tiles, 4x4 microtiles) for clean attribution.

#define NB   256
#define HH   512
#define FH   2048   // 4H
#define K3   1536   // 3H (i,f,g rows of W_ih)
#define CG_ITERS 4

// ---------------- scratch (static device memory; no allocs allowed) --------
__device__ float g_z [NB * FH];      // pre-activation gates
__device__ float g_ci[NB * HH];
__device__ float g_cf[NB * HH];
__device__ float g_cg[NB * HH];
__device__ float g_T [NB * K3];      // T[n][m*512+j] = c_m[n,j] * d[n,j]
__device__ float g_u [NB * HH];      // u = G^T d   (atomic accumulated)
__device__ float g_s [NB * HH];      // s = G u     (atomic accumulated)
__device__ float g_r [NB * HH];      // CG residual
__device__ float g_d [NB * HH];      // CG direction
__device__ float g_rs[NB];           // per-row r.r

// ---------------- block reduction over 512 threads -------------------------
__device__ __forceinline__ float blk_reduce_512(float v) {
    __shared__ float sm[16];
    int lane = threadIdx.x & 31;
    int w    = threadIdx.x >> 5;
    #pragma unroll
    for (int o = 16; o > 0; o >>= 1) v += __shfl_down_sync(0xffffffffu, v, o);
    __syncthreads();
    if (lane == 0) sm[w] = v;
    __syncthreads();
    if (threadIdx.x == 0) {
        float s = 0.f;
        #pragma unroll
        for (int i = 0; i < 16; ++i) s += sm[i];
        sm[0] = s;
    }
    __syncthreads();
    return sm[0];
}

// ---------------- GEMM 1: z = x@Wih^T + hx@Whh^T + b_ih + b_hh -------------
// out tile 64(n) x 64(r), 4x4/thread, K = 512+512. grid (4,32), 256 threads.
__global__ void __launch_bounds__(256) gemm_z_kernel(
    const float* __restrict__ x,   const float* __restrict__ hx,
    const float* __restrict__ Wih, const float* __restrict__ Whh,
    const float* __restrict__ bih, const float* __restrict__ bhh)
{
    __shared__ float As[64][17];                      // As[nn][kk]
    __shared__ __align__(16) float Bs[16][68];        // Bs[kk][rr]
    const int n0 = blockIdx.x * 64;
    const int r0 = blockIdx.y * 64;
    const int t  = threadIdx.x;
    const int tx = t & 15;          // 16 col-groups of 4
    const int ty = t >> 4;          // 16 row-groups of 4
    float acc[4][4];
    #pragma unroll
    for (int i = 0; i < 4; ++i)
        #pragma unroll
        for (int c = 0; c < 4; ++c) acc[i][c] = 0.f;

    for (int src = 0; src < 2; ++src) {
        const float* __restrict__ A = src ? hx  : x;
        const float* __restrict__ B = src ? Whh : Wih;
        for (int kb = 0; kb < 512; kb += 16) {
            {   // A tile 64x16 natural
                int kk = t & 15, nr = t >> 4;
                #pragma unroll
                for (int i = 0; i < 4; ++i)
                    As[nr + 16*i][kk] = A[(n0 + nr + 16*i) * 512 + kb + kk];
            }
            {   // B tile transposed: Bs[kk][rr] = W[r0+rr][kb+kk]
                int kk = t & 15, rr = t >> 4;
                #pragma unroll
                for (int i = 0; i < 4; ++i)
                    Bs[kk][rr + 16*i] = B[(r0 + rr + 16*i) * 512 + kb + kk];
            }
            __syncthreads();
            #pragma unroll
            for (int kk = 0; kk < 16; ++kk) {
                float a0 = As[ty*4  ][kk];
                float a1 = As[ty*4+1][kk];
                float a2 = As[ty*4+2][kk];
                float a3 = As[ty*4+3][kk];
                float4 b = *(const float4*)&Bs[kk][tx*4];
                acc[0][0] += a0*b.x; acc[0][1] += a0*b.y; acc[0][2] += a0*b.z; acc[0][3] += a0*b.w;
                acc[1][0] += a1*b.x; acc[1][1] += a1*b.y; acc[1][2] += a1*b.z; acc[1][3] += a1*b.w;
                acc[2][0] += a2*b.x; acc[2][1] += a2*b.y; acc[2][2] += a2*b.z; acc[2][3] += a2*b.w;
                acc[3][0] += a3*b.x; acc[3][1] += a3*b.y; acc[3][2] += a3*b.z; acc[3][3] += a3*b.w;
            }
            __syncthreads();
        }
    }
    #pragma unroll
    for (int i = 0; i < 4; ++i) {
        int n = n0 + ty*4 + i;
        #pragma unroll
        for (int c = 0; c < 4; ++c) {
            int r = r0 + tx*4 + c;
            g_z[n * FH + r] = acc[i][c] + __ldg(&bih[r]) + __ldg(&bhh[r]);
        }
    }
}

// ---------------- gates + CG init ------------------------------------------
__global__ void __launch_bounds__(512) gates_init_kernel(
    const float* __restrict__ cx, float* __restrict__ out)
{
    const int n = blockIdx.x, j = threadIdx.x;
    const int idx  = n * HH + j;
    const int zrow = n * FH;
    const float zi = g_z[zrow + j];
    const float zf = g_z[zrow + 512 + j];
    const float zg = g_z[zrow + 1024 + j];
    const float zo = g_z[zrow + 1536 + j];
    const float cxx = cx[idx];

    const float i  = 1.f / (1.f + expf(-zi));
    const float f  = 1.f / (1.f + expf(-zf));
    const float gg = tanhf(zg);
    const float o  = 1.f / (1.f + expf(-zo));

    const float c  = f * cxx + i * gg;
    const float h  = o * tanhf(c);

    out[idx] = h;                       // h_new
    out[NB*HH + idx] = 0.f;             // p0 = 0 (prox_c)

    const float ci_ = i  * (1.f - i ) * gg;
    const float cf_ = f  * (1.f - f ) * cxx;
    const float cg_ = (1.f - gg*gg) * i;
    g_ci[idx] = ci_;  g_cf[idx] = cf_;  g_cg[idx] = cg_;

    g_r[idx] = c;  g_d[idx] = c;
    const int trow = n * K3;
    g_T[trow +        j] = ci_ * c;
    g_T[trow +  512 + j] = cf_ * c;
    g_T[trow + 1024 + j] = cg_ * c;
    g_u[idx] = 0.f;  g_s[idx] = 0.f;

    float rs = blk_reduce_512(c * c);
    if (j == 0) g_rs[n] = rs;
}

// ---------------- GEMM A: u = T @ Wih[0:1536]  (K=1536, k-split 8) ---------
// out tile 64(n) x 64(k), 4x4/thread, grid (4,8,8), 256 threads, atomics.
__global__ void __launch_bounds__(256) gemm_A_kernel(const float* __restrict__ Wih)
{
    __shared__ float As[64][17];                      // As[nn][kk] = T
    __shared__ __align__(16) float Bs[16][68];        // Bs[kk][cc] = Wih
    const int n0 = blockIdx.x * 64;
    const int k0 = blockIdx.y * 64;
    const int jbase = blockIdx.z * 192;
    const int t  = threadIdx.x;
    const int tx = t & 15, ty = t >> 4;
    float acc[4][4];
    #pragma unroll
    for (int i = 0; i < 4; ++i)
        #pragma unroll
        for (int c = 0; c < 4; ++c) acc[i][c] = 0.f;

    for (int jb = jbase; jb < jbase + 192; jb += 16) {
        {   // A tile 64x16 natural
            int kk = t & 15, nr = t >> 4;
            #pragma unroll
            for (int i = 0; i < 4; ++i)
                As[nr + 16*i][kk] = g_T[(n0 + nr + 16*i) * K3 + jb + kk];
        }
        {   // B tile natural: Bs[kk][cc] = Wih[jb+kk][k0+cc]
            int cc = t & 63, kr = t >> 6;             // kr 0..3
            #pragma unroll
            for (int i = 0; i < 4; ++i)
                Bs[kr + 4*i][cc] = Wih[(jb + kr + 4*i) * 512 + k0 + cc];
        }
        __syncthreads();
        #pragma unroll
        for (int kk = 0; kk < 16; ++kk) {
            float a0 = As[ty*4  ][kk];
            float a1 = As[ty*4+1][kk];
            float a2 = As[ty*4+2][kk];
            float a3 = As[ty*4+3][kk];
            float4 b = *(const float4*)&Bs[kk][tx*4];
            acc[0][0] += a0*b.x; acc[0][1] += a0*b.y; acc[0][2] += a0*b.z; acc[0][3] += a0*b.w;
            acc[1][0] += a1*b.x; acc[1][1] += a1*b.y; acc[1][2] += a1*b.z; acc[1][3] += a1*b.w;
            acc[2][0] += a2*b.x; acc[2][1] += a2*b.y; acc[2][2] += a2*b.z; acc[2][3] += a2*b.w;
            acc[3][0] += a3*b.x; acc[3][1] += a3*b.y; acc[3][2] += a3*b.z; acc[3][3] += a3*b.w;
        }
        __syncthreads();
    }
    #pragma unroll
    for (int i = 0; i < 4; ++i) {
        int n = n0 + ty*4 + i;
        #pragma unroll
        for (int c = 0; c < 4; ++c)
            atomicAdd(&g_u[n * HH + k0 + tx*4 + c], acc[i][c]);
    }
}

// ---------------- GEMM B: s = ci.(Wi u) + cf.(Wf u) + cg.(Wg u) ------------
// out tile 64(n) x 64(j), 4x4/thread, K=512 k-split 8, grid (4,8,8).
__global__ void __launch_bounds__(256) gemm_B_kernel(const float* __restrict__ Wih)
{
    __shared__ float As[64][17];                      // u
    __shared__ __align__(16) float Bs[3][16][68];     // Wi/Wf/Wg transposed
    const int n0 = blockIdx.x * 64;
    const int j0 = blockIdx.y * 64;
    const int kbase = blockIdx.z * 64;
    const int t  = threadIdx.x;
    const int tx = t & 15, ty = t >> 4;
    float acc[3][4][4];
    #pragma unroll
    for (int m = 0; m < 3; ++m)
        #pragma unroll
        for (int i = 0; i < 4; ++i)
            #pragma unroll
            for (int c = 0; c < 4; ++c) acc[m][i][c] = 0.f;

    for (int kb = kbase; kb < kbase + 64; kb += 16) {
        {   // A tile: u 64x16 natural
            int kk = t & 15, nr = t >> 4;
            #pragma unroll
            for (int i = 0; i < 4; ++i)
                As[nr + 16*i][kk] = g_u[(n0 + nr + 16*i) * HH + kb + kk];
        }
        {   // B tiles transposed: Bs[m][kk][jj] = Wih[m*512+j0+jj][kb+kk]
            int kk = t & 15, jj = t >> 4;
            #pragma unroll
            for (int m = 0; m < 3; ++m)
                #pragma unroll
                for (int i = 0; i < 4; ++i)
                    Bs[m][kk][jj + 16*i] =
                        Wih[(m*512 + j0 + jj + 16*i) * 512 + kb + kk];
        }
        __syncthreads();
        #pragma unroll
        for (int kk = 0; kk < 16; ++kk) {
            float a0 = As[ty*4  ][kk];
            float a1 = As[ty*4+1][kk];
            float a2 = As[ty*4+2][kk];
            float a3 = As[ty*4+3][kk];
            float4 bi = *(const float4*)&Bs[0][kk][tx*4];
            float4 bf = *(const float4*)&Bs[1][kk][tx*4];
            float4 bg = *(const float4*)&Bs[2][kk][tx*4];
            acc[0][0][0] += a0*bi.x; acc[0][0][1] += a0*bi.y; acc[0][0][2] += a0*bi.z; acc[0][0][3] += a0*bi.w;
            acc[0][1][0] += a1*bi.x; acc[0][1][1] += a1*bi.y; acc[0][1][2] += a1*bi.z; acc[0][1][3] += a1*bi.w;
            acc[0][2][0] += a2*bi.x; acc[0][2][1] += a2*bi.y; acc[0][2][2] += a2*bi.z; acc[0][2][3] += a2*bi.w;
            acc[0][3][0] += a3*bi.x; acc[0][3][1] += a3*bi.y; acc[0][3][2] += a3*bi.z; acc[0][3][3] += a3*bi.w;
            acc[1][0][0] += a0*bf.x; acc[1][0][1] += a0*bf.y; acc[1][0][2] += a0*bf.z; acc[1][0][3] += a0*bf.w;
            acc[1][1][0] += a1*bf.x; acc[1][1][1] += a1*bf.y; acc[1][1][2] += a1*bf.z; acc[1][1][3] += a1*bf.w;
            acc[1][2][0] += a2*bf.x; acc[1][2][1] += a2*bf.y; acc[1][2][2] += a2*bf.z; acc[1][2][3] += a2*bf.w;
            acc[1][3][0] += a3*bf.x; acc[1][3][1] += a3*bf.y; acc[1][3][2] += a3*bf.z; acc[1][3][3] += a3*bf.w;
            acc[2][0][0] += a0*bg.x; acc[2][0][1] += a0*bg.y; acc[2][0][2] += a0*bg.z; acc[2][0][3] += a0*bg.w;
            acc[2][1][0] += a1*bg.x; acc[2][1][1] += a1*bg.y; acc[2][1][2] += a1*bg.z; acc[2][1][3] += a1*bg.w;
            acc[2][2][0] += a2*bg.x; acc[2][2][1] += a2*bg.y; acc[2][2][2] += a2*bg.z; acc[2][2][3] += a2*bg.w;
            acc[2][3][0] += a3*bg.x; acc[2][3][1] += a3*bg.y; acc[2][3][2] += a3*bg.z; acc[2][3][3] += a3*bg.w;
        }
        __syncthreads();
    }
    #pragma unroll
    for (int i = 0; i < 4; ++i) {
        int n = n0 + ty*4 + i;
        #pragma unroll
        for (int c = 0; c < 4; ++c) {
            int idx = n * HH + j0 + tx*4 + c;
            float s = g_ci[idx]*acc[0][i][c]
                    + g_cf[idx]*acc[1][i][c]
                    + g_cg[idx]*acc[2][i][c];
            atomicAdd(&g_s[idx], s);
        }
    }
}

// ---------------- CG update (one block per batch row) -----------------------
__global__ void __launch_bounds__(512) cg_update_kernel(float* __restrict__ p)
{
    const int n = blockIdx.x, j = threadIdx.x;
    const int idx = n * HH + j;

    const float dj = g_d[idx];
    const float qj = dj + g_s[idx];          // q = A d = d + G G^T d
    const float dq = blk_reduce_512(dj * qj);
    const float rsold = g_rs[n];
    const float alpha = (dq > 0.f) ? rsold / dq : 0.f;

    p[idx] += alpha * dj;
    const float rj = g_r[idx] - alpha * qj;
    g_r[idx] = rj;

    const float rsnew = blk_reduce_512(rj * rj);
    const float beta  = (rsold > 1e-30f) ? rsnew / rsold : 0.f;
    const float dnew  = rj + beta * dj;
    g_d[idx] = dnew;
    if (j == 0) g_rs[n] = rsnew;

    const int trow = n * K3;
    g_T[trow +        j] = g_ci[idx] * dnew;
    g_T[trow +  512 + j] = g_cf[idx] * dnew;
    g_T[trow + 1024 + j] = g_cg[idx] * dnew;
    g_u[idx] = 0.f;
    g_s[idx] = 0.f;
}

// ---------------- launch ----------------------------------------------------
extern "C" void kernel_launch(void* const* d_in, const int* in_sizes, int n_in,
                              void* d_out, int out_size)
{
    const float* x   = (const float*)d_in[0];
    const float* hx  = (const float*)d_in[1];
    const float* cx  = (const float*)d_in[2];
    const float* Wih = (const float*)d_in[3];
    const float* Whh = (const float*)d_in[4];
    const float* bih = (const float*)d_in[5];
    const float* bhh = (const float*)d_in[6];
    float* out = (float*)d_out;                 // [h_new | prox_c]
    float* p   = out + NB * HH;

    gemm_z_kernel<<<dim3(4, 32), 256>>>(x, hx, Wih, Whh, bih, bhh);
    gates_init_kernel<<<NB, 512>>>(cx, out);
    for (int it = 0; it < CG_ITERS; ++it) {
        gemm_A_kernel<<<dim3(4, 8, 8), 256>>>(Wih);
        gemm_B_kernel<<<dim3(4, 8, 8), 256>>>(Wih);
        cg_update_kernel<<<NB, 512>>>(p);
    }
}

// round 14
// speedup vs baseline: 1.4864x; 1.4864x over previous
#include <cuda_runtime.h>

// ProximalLSTMCell: N=256, D=512, H=512, EPS=1
// Matrix-free CG on (I + G G^T) p = c_new; G_n = diag(ci)Wi+diag(cf)Wf+diag(cg)Wg.
// R12 change-set (unmeasured due to broker failure; resubmitted verbatim):
//   CG_ITERS=4 confirmed (rel_err 7.1e-5, rho~0.09; 3 iters would be ~8e-4).
//   gemm_B restructured: s = sum_m c_m.(W_m u) decomposed per gate m ->
//   16 accumulators/thread instead of 48, regs 106->~70, occ 2->3 blocks/SM.

#define NB   256
#define HH   512
#define FH   2048   // 4H
#define K3   1536   // 3H (i,f,g rows of W_ih)
#define CG_ITERS 4

// ---------------- scratch (static device memory; no allocs allowed) --------
__device__ float g_z [NB * FH];      // pre-activation gates
__device__ float g_ci[NB * HH];
__device__ float g_cf[NB * HH];
__device__ float g_cg[NB * HH];
__device__ float g_T [NB * K3];      // T[n][m*512+j] = c_m[n,j] * d[n,j]
__device__ float g_u [NB * HH];      // u = G^T d   (atomic accumulated)
__device__ float g_s [NB * HH];      // s = G u     (atomic accumulated)
__device__ float g_r [NB * HH];      // CG residual
__device__ float g_d [NB * HH];      // CG direction
__device__ float g_rs[NB];           // per-row r.r

// ---------------- block reduction over 512 threads -------------------------
__device__ __forceinline__ float blk_reduce_512(float v) {
    __shared__ float sm[16];
    int lane = threadIdx.x & 31;
    int w    = threadIdx.x >> 5;
    #pragma unroll
    for (int o = 16; o > 0; o >>= 1) v += __shfl_down_sync(0xffffffffu, v, o);
    __syncthreads();
    if (lane == 0) sm[w] = v;
    __syncthreads();
    if (threadIdx.x == 0) {
        float s = 0.f;
        #pragma unroll
        for (int i = 0; i < 16; ++i) s += sm[i];
        sm[0] = s;
    }
    __syncthreads();
    return sm[0];
}

// ---------------- GEMM 1: z = x@Wih^T + hx@Whh^T + b_ih + b_hh -------------
// out tile 64(n) x 64(r), 4x4/thread, K = 512+512. grid (4,32), 256 threads.
__global__ void __launch_bounds__(256) gemm_z_kernel(
    const float* __restrict__ x,   const float* __restrict__ hx,
    const float* __restrict__ Wih, const float* __restrict__ Whh,
    const float* __restrict__ bih, const float* __restrict__ bhh)
{
    __shared__ float As[64][17];                      // As[nn][kk]
    __shared__ __align__(16) float Bs[16][68];        // Bs[kk][rr]
    const int n0 = blockIdx.x * 64;
    const int r0 = blockIdx.y * 64;
    const int t  = threadIdx.x;
    const int tx = t & 15;          // 16 col-groups of 4
    const int ty = t >> 4;          // 16 row-groups of 4
    float acc[4][4];
    #pragma unroll
    for (int i = 0; i < 4; ++i)
        #pragma unroll
        for (int c = 0; c < 4; ++c) acc[i][c] = 0.f;

    for (int src = 0; src < 2; ++src) {
        const float* __restrict__ A = src ? hx  : x;
        const float* __restrict__ B = src ? Whh : Wih;
        for (int kb = 0; kb < 512; kb += 16) {
            {   // A tile 64x16 natural
                int kk = t & 15, nr = t >> 4;
                #pragma unroll
                for (int i = 0; i < 4; ++i)
                    As[nr + 16*i][kk] = A[(n0 + nr + 16*i) * 512 + kb + kk];
            }
            {   // B tile transposed: Bs[kk][rr] = W[r0+rr][kb+kk]
                int kk = t & 15, rr = t >> 4;
                #pragma unroll
                for (int i = 0; i < 4; ++i)
                    Bs[kk][rr + 16*i] = B[(r0 + rr + 16*i) * 512 + kb + kk];
            }
            __syncthreads();
            #pragma unroll
            for (int kk = 0; kk < 16; ++kk) {
                float a0 = As[ty*4  ][kk];
                float a1 = As[ty*4+1][kk];
                float a2 = As[ty*4+2][kk];
                float a3 = As[ty*4+3][kk];
                float4 b = *(const float4*)&Bs[kk][tx*4];
                acc[0][0] += a0*b.x; acc[0][1] += a0*b.y; acc[0][2] += a0*b.z; acc[0][3] += a0*b.w;
                acc[1][0] += a1*b.x; acc[1][1] += a1*b.y; acc[1][2] += a1*b.z; acc[1][3] += a1*b.w;
                acc[2][0] += a2*b.x; acc[2][1] += a2*b.y; acc[2][2] += a2*b.z; acc[2][3] += a2*b.w;
                acc[3][0] += a3*b.x; acc[3][1] += a3*b.y; acc[3][2] += a3*b.z; acc[3][3] += a3*b.w;
            }
            __syncthreads();
        }
    }
    #pragma unroll
    for (int i = 0; i < 4; ++i) {
        int n = n0 + ty*4 + i;
        #pragma unroll
        for (int c = 0; c < 4; ++c) {
            int r = r0 + tx*4 + c;
            g_z[n * FH + r] = acc[i][c] + __ldg(&bih[r]) + __ldg(&bhh[r]);
        }
    }
}

// ---------------- gates + CG init ------------------------------------------
__global__ void __launch_bounds__(512) gates_init_kernel(
    const float* __restrict__ cx, float* __restrict__ out)
{
    const int n = blockIdx.x, j = threadIdx.x;
    const int idx  = n * HH + j;
    const int zrow = n * FH;
    const float zi = g_z[zrow + j];
    const float zf = g_z[zrow + 512 + j];
    const float zg = g_z[zrow + 1024 + j];
    const float zo = g_z[zrow + 1536 + j];
    const float cxx = cx[idx];

    const float i  = 1.f / (1.f + expf(-zi));
    const float f  = 1.f / (1.f + expf(-zf));
    const float gg = tanhf(zg);
    const float o  = 1.f / (1.f + expf(-zo));

    const float c  = f * cxx + i * gg;
    const float h  = o * tanhf(c);

    out[idx] = h;                       // h_new
    out[NB*HH + idx] = 0.f;             // p0 = 0 (prox_c)

    const float ci_ = i  * (1.f - i ) * gg;
    const float cf_ = f  * (1.f - f ) * cxx;
    const float cg_ = (1.f - gg*gg) * i;
    g_ci[idx] = ci_;  g_cf[idx] = cf_;  g_cg[idx] = cg_;

    g_r[idx] = c;  g_d[idx] = c;
    const int trow = n * K3;
    g_T[trow +        j] = ci_ * c;
    g_T[trow +  512 + j] = cf_ * c;
    g_T[trow + 1024 + j] = cg_ * c;
    g_u[idx] = 0.f;  g_s[idx] = 0.f;

    float rs = blk_reduce_512(c * c);
    if (j == 0) g_rs[n] = rs;
}

// ---------------- GEMM A: u = T @ Wih[0:1536]  (K=1536, k-split 8) ---------
// out tile 64(n) x 64(k), 4x4/thread, grid (4,8,8), 256 threads, atomics.
__global__ void __launch_bounds__(256) gemm_A_kernel(const float* __restrict__ Wih)
{
    __shared__ float As[64][17];                      // As[nn][kk] = T
    __shared__ __align__(16) float Bs[16][68];        // Bs[kk][cc] = Wih
    const int n0 = blockIdx.x * 64;
    const int k0 = blockIdx.y * 64;
    const int jbase = blockIdx.z * 192;
    const int t  = threadIdx.x;
    const int tx = t & 15, ty = t >> 4;
    float acc[4][4];
    #pragma unroll
    for (int i = 0; i < 4; ++i)
        #pragma unroll
        for (int c = 0; c < 4; ++c) acc[i][c] = 0.f;

    for (int jb = jbase; jb < jbase + 192; jb += 16) {
        {   // A tile 64x16 natural
            int kk = t & 15, nr = t >> 4;
            #pragma unroll
            for (int i = 0; i < 4; ++i)
                As[nr + 16*i][kk] = g_T[(n0 + nr + 16*i) * K3 + jb + kk];
        }
        {   // B tile natural: Bs[kk][cc] = Wih[jb+kk][k0+cc]
            int cc = t & 63, kr = t >> 6;             // kr 0..3
            #pragma unroll
            for (int i = 0; i < 4; ++i)
                Bs[kr + 4*i][cc] = Wih[(jb + kr + 4*i) * 512 + k0 + cc];
        }
        __syncthreads();
        #pragma unroll
        for (int kk = 0; kk < 16; ++kk) {
            float a0 = As[ty*4  ][kk];
            float a1 = As[ty*4+1][kk];
            float a2 = As[ty*4+2][kk];
            float a3 = As[ty*4+3][kk];
            float4 b = *(const float4*)&Bs[kk][tx*4];
            acc[0][0] += a0*b.x; acc[0][1] += a0*b.y; acc[0][2] += a0*b.z; acc[0][3] += a0*b.w;
            acc[1][0] += a1*b.x; acc[1][1] += a1*b.y; acc[1][2] += a1*b.z; acc[1][3] += a1*b.w;
            acc[2][0] += a2*b.x; acc[2][1] += a2*b.y; acc[2][2] += a2*b.z; acc[2][3] += a2*b.w;
            acc[3][0] += a3*b.x; acc[3][1] += a3*b.y; acc[3][2] += a3*b.z; acc[3][3] += a3*b.w;
        }
        __syncthreads();
    }
    #pragma unroll
    for (int i = 0; i < 4; ++i) {
        int n = n0 + ty*4 + i;
        #pragma unroll
        for (int c = 0; c < 4; ++c)
            atomicAdd(&g_u[n * HH + k0 + tx*4 + c], acc[i][c]);
    }
}

// ---------------- GEMM B: s += c_m . (W_m u), one gate m per block ----------
// out tile 64(n) x 64(j), 4x4/thread (16 accums). blockIdx.z = ks*3 + m,
// ks in [0,4) K-slices of 128, m in {0:i, 1:f, 2:g}. grid (4,8,12), atomics.
__global__ void __launch_bounds__(256) gemm_B_kernel(const float* __restrict__ Wih)
{
    __shared__ float As[64][17];                      // u
    __shared__ __align__(16) float Bs[16][68];        // W_m transposed
    const int n0 = blockIdx.x * 64;
    const int j0 = blockIdx.y * 64;
    const int m     = blockIdx.z % 3;
    const int kbase = (blockIdx.z / 3) * 128;
    const int t  = threadIdx.x;
    const int tx = t & 15, ty = t >> 4;
    const float* __restrict__ cm = (m == 0) ? g_ci : (m == 1) ? g_cf : g_cg;
    float acc[4][4];
    #pragma unroll
    for (int i = 0; i < 4; ++i)
        #pragma unroll
        for (int c = 0; c < 4; ++c) acc[i][c] = 0.f;

    for (int kb = kbase; kb < kbase + 128; kb += 16) {
        {   // A tile: u 64x16 natural
            int kk = t & 15, nr = t >> 4;
            #pragma unroll
            for (int i = 0; i < 4; ++i)
                As[nr + 16*i][kk] = g_u[(n0 + nr + 16*i) * HH + kb + kk];
        }
        {   // B tile transposed: Bs[kk][jj] = Wih[m*512+j0+jj][kb+kk]
            int kk = t & 15, jj = t >> 4;
            #pragma unroll
            for (int i = 0; i < 4; ++i)
                Bs[kk][jj + 16*i] =
                    Wih[(m*512 + j0 + jj + 16*i) * 512 + kb + kk];
        }
        __syncthreads();
        #pragma unroll
        for (int kk = 0; kk < 16; ++kk) {
            float a0 = As[ty*4  ][kk];
            float a1 = As[ty*4+1][kk];
            float a2 = As[ty*4+2][kk];
            float a3 = As[ty*4+3][kk];
            float4 b = *(const float4*)&Bs[kk][tx*4];
            acc[0][0] += a0*b.x; acc[0][1] += a0*b.y; acc[0][2] += a0*b.z; acc[0][3] += a0*b.w;
            acc[1][0] += a1*b.x; acc[1][1] += a1*b.y; acc[1][2] += a1*b.z; acc[1][3] += a1*b.w;
            acc[2][0] += a2*b.x; acc[2][1] += a2*b.y; acc[2][2] += a2*b.z; acc[2][3] += a2*b.w;
            acc[3][0] += a3*b.x; acc[3][1] += a3*b.y; acc[3][2] += a3*b.z; acc[3][3] += a3*b.w;
        }
        __syncthreads();
    }
    #pragma unroll
    for (int i = 0; i < 4; ++i) {
        int n = n0 + ty*4 + i;
        #pragma unroll
        for (int c = 0; c < 4; ++c) {
            int idx = n * HH + j0 + tx*4 + c;
            atomicAdd(&g_s[idx], cm[idx] * acc[i][c]);
        }
    }
}

// ---------------- CG update (one block per batch row) -----------------------
__global__ void __launch_bounds__(512) cg_update_kernel(float* __restrict__ p)
{
    const int n = blockIdx.x, j = threadIdx.x;
    const int idx = n * HH + j;

    const float dj = g_d[idx];
    const float qj = dj + g_s[idx];          // q = A d = d + G G^T d
    const float dq = blk_reduce_512(dj * qj);
    const float rsold = g_rs[n];
    const float alpha = (dq > 0.f) ? rsold / dq : 0.f;

    p[idx] += alpha * dj;
    const float rj = g_r[idx] - alpha * qj;
    g_r[idx] = rj;

    const float rsnew = blk_reduce_512(rj * rj);
    const float beta  = (rsold > 1e-30f) ? rsnew / rsold : 0.f;
    const float dnew  = rj + beta * dj;
    g_d[idx] = dnew;
    if (j == 0) g_rs[n] = rsnew;

    const int trow = n * K3;
    g_T[trow +        j] = g_ci[idx] * dnew;
    g_T[trow +  512 + j] = g_cf[idx] * dnew;
    g_T[trow + 1024 + j] = g_cg[idx] * dnew;
    g_u[idx] = 0.f;
    g_s[idx] = 0.f;
}

// ---------------- launch ----------------------------------------------------
extern "C" void kernel_launch(void* const* d_in, const int* in_sizes, int n_in,
                              void* d_out, int out_size)
{
    const float* x   = (const float*)d_in[0];
    const float* hx  = (const float*)d_in[1];
    const float* cx  = (const float*)d_in[2];
    const float* Wih = (const float*)d_in[3];
    const float* Whh = (const float*)d_in[4];
    const float* bih = (const float*)d_in[5];
    const float* bhh = (const float*)d_in[6];
    float* out = (float*)d_out;                 // [h_new | prox_c]
    float* p   = out + NB * HH;

    gemm_z_kernel<<<dim3(4, 32), 256>>>(x, hx, Wih, Whh, bih, bhh);
    gates_init_kernel<<<NB, 512>>>(cx, out);
    for (int it = 0; it < CG_ITERS; ++it) {
        gemm_A_kernel<<<dim3(4, 8, 8), 256>>>(Wih);
        gemm_B_kernel<<<dim3(4, 8, 12), 256>>>(Wih);
        cg_update_kernel<<<NB, 512>>>(p);
    }
}